// round 15
// baseline (speedup 1.0000x reference)
#include <cuda_runtime.h>
#include <cuda_bf16.h>
#include <cuda_fp16.h>
#include <cstdint>

#define N_TOK  8192
#define DMODEL 1024
#define NE     8
#define CAP    0.8f

#define TM 128
#define TN 64
#define KC 32
#define NCHUNK (DMODEL / KC)   // 32
#define STAGES 4

// ---------------- device scratch (allocation-free rule) ----------------
__device__ int   g_count[NE];
__device__ int   g_list[NE * N_TOK];
__device__ float g_wt  [NE * N_TOK];
__device__ __half g_xh[(size_t)N_TOK * DMODEL];
__device__ __half g_w1h[(size_t)NE * DMODEL * DMODEL];   // [e][k][n] native layout
__device__ __half g_w2h[(size_t)NE * DMODEL * DMODEL];   // [e][k][n] native layout
__device__ __half g_h  [(size_t)NE * N_TOK * DMODEL];

// ---------------- helpers ----------------
__device__ __forceinline__ uint32_t smem_u32(const void* p) {
    uint32_t a;
    asm("{ .reg .u64 t; cvta.to.shared.u64 t, %1; cvt.u32.u64 %0, t; }" : "=r"(a) : "l"(p));
    return a;
}
__device__ __forceinline__ uint32_t sw64(uint32_t off)  { return off ^ ((off >> 3) & 0x30); }
__device__ __forceinline__ uint32_t sw128(uint32_t off) { return off ^ ((off >> 3) & 0x70); }

#define CP16(dst, src) \
    asm volatile("cp.async.cg.shared.global [%0], [%1], 16;" :: "r"(dst), "l"(src) : "memory")
#define CP_COMMIT() asm volatile("cp.async.commit_group;" ::: "memory")
#define CP_WAIT2()  asm volatile("cp.async.wait_group 2;" ::: "memory")

__device__ __forceinline__ void ldsm4(uint32_t (&r)[4], uint32_t addr) {
    asm volatile("ldmatrix.sync.aligned.m8n8.x4.shared.b16 {%0,%1,%2,%3}, [%4];"
                 : "=r"(r[0]), "=r"(r[1]), "=r"(r[2]), "=r"(r[3]) : "r"(addr));
}
__device__ __forceinline__ void ldsm4t(uint32_t (&r)[4], uint32_t addr) {
    asm volatile("ldmatrix.sync.aligned.m8n8.x4.trans.shared.b16 {%0,%1,%2,%3}, [%4];"
                 : "=r"(r[0]), "=r"(r[1]), "=r"(r[2]), "=r"(r[3]) : "r"(addr));
}
__device__ __forceinline__ void mma16816(float* d, const uint32_t* a, uint32_t b0, uint32_t b1) {
    asm volatile(
        "mma.sync.aligned.m16n8k16.row.col.f32.f16.f16.f32 "
        "{%0,%1,%2,%3}, {%4,%5,%6,%7}, {%8,%9}, {%0,%1,%2,%3};"
        : "+f"(d[0]), "+f"(d[1]), "+f"(d[2]), "+f"(d[3])
        : "r"(a[0]), "r"(a[1]), "r"(a[2]), "r"(a[3]), "r"(b0), "r"(b1));
}
__device__ __forceinline__ void red_add_v4(float* gptr, float4 v) {
    asm volatile("red.global.add.v4.f32 [%0], {%1, %2, %3, %4};"
                 :: "l"(gptr), "f"(v.x), "f"(v.y), "f"(v.z), "f"(v.w) : "memory");
}

// ---------------- zero counts ----------------
__global__ void zero_counts_kernel() {
    if (threadIdx.x < NE) g_count[threadIdx.x] = 0;
}

// ---------------- pre: router + W1 convert + out zero (one launch) ----------------
// blocks [0, 1024): router ; [1024, 3072): W1 convert ; [3072, 4096): zero out
#define ROUTER_BLOCKS 1024
#define W1CONV_BLOCKS 2048
#define OUTZ_BLOCKS   1024

__global__ void pre_kernel(const float* __restrict__ x,
                           const float* __restrict__ Wsel,
                           const float* __restrict__ bsel,
                           const float* __restrict__ W1,
                           float* __restrict__ out) {
    int bid = blockIdx.x;
    if (bid >= ROUTER_BLOCKS + W1CONV_BLOCKS) {
        size_t base = (size_t)(bid - ROUTER_BLOCKS - W1CONV_BLOCKS) * 2048 + threadIdx.x;
        float4 z = make_float4(0.f, 0.f, 0.f, 0.f);
#pragma unroll
        for (int it = 0; it < 8; it++)
            reinterpret_cast<float4*>(out)[base + (size_t)it * 256] = z;
        return;
    }
    if (bid >= ROUTER_BLOCKS) {
        size_t base = (size_t)(bid - ROUTER_BLOCKS) * 1024 + threadIdx.x;
#pragma unroll
        for (int it = 0; it < 4; it++) {
            size_t i = base + (size_t)it * 256;
            float4 v = reinterpret_cast<const float4*>(W1)[i];
            __half h[4];
            h[0] = __float2half(v.x); h[1] = __float2half(v.y);
            h[2] = __float2half(v.z); h[3] = __float2half(v.w);
            *reinterpret_cast<uint2*>(&g_w1h[i * 4]) = *reinterpret_cast<uint2*>(h);
        }
        return;
    }

    // ---- router: 8 warps = 8 tokens per block ----
    int warp = threadIdx.x >> 5;
    int lane = threadIdx.x & 31;
    int n = bid * 8 + warp;

    const float* xr = x + (size_t)n * DMODEL;
    __half* xo = g_xh + (size_t)n * DMODEL;
    float acc[NE];
#pragma unroll
    for (int e = 0; e < NE; e++) acc[e] = 0.f;
    for (int d = lane * 2; d < DMODEL; d += 64) {
        float2 xv = *reinterpret_cast<const float2*>(xr + d);
        __half2 hx;
        hx.x = __float2half(xv.x); hx.y = __float2half(xv.y);
        *reinterpret_cast<__half2*>(xo + d) = hx;
        const float4* w4 = reinterpret_cast<const float4*>(Wsel + (size_t)d * NE);
        float4 a0 = w4[0], a1 = w4[1];
        float4 c0 = w4[2], c1 = w4[3];
        acc[0] += xv.x * a0.x; acc[1] += xv.x * a0.y; acc[2] += xv.x * a0.z; acc[3] += xv.x * a0.w;
        acc[4] += xv.x * a1.x; acc[5] += xv.x * a1.y; acc[6] += xv.x * a1.z; acc[7] += xv.x * a1.w;
        acc[0] += xv.y * c0.x; acc[1] += xv.y * c0.y; acc[2] += xv.y * c0.z; acc[3] += xv.y * c0.w;
        acc[4] += xv.y * c1.x; acc[5] += xv.y * c1.y; acc[6] += xv.y * c1.z; acc[7] += xv.y * c1.w;
    }
#pragma unroll
    for (int off = 16; off; off >>= 1)
#pragma unroll
        for (int e = 0; e < NE; e++) acc[e] += __shfl_xor_sync(0xffffffffu, acc[e], off);

    if (lane == 0) {
        float w[NE];
        float mx = -1e30f;
#pragma unroll
        for (int e = 0; e < NE; e++) { w[e] = acc[e] + bsel[e]; mx = fmaxf(mx, w[e]); }
        float s = 0.f;
#pragma unroll
        for (int e = 0; e < NE; e++) { w[e] = expf(w[e] - mx); s += w[e]; }
        float inv = 1.f / s;
#pragma unroll
        for (int e = 0; e < NE; e++) w[e] *= inv;

        int ord[NE]; bool used[NE];
#pragma unroll
        for (int e = 0; e < NE; e++) used[e] = false;
#pragma unroll
        for (int j = 0; j < NE; j++) {
            int best = -1; float bv = -1e30f;
#pragma unroll
            for (int e = 0; e < NE; e++)
                if (!used[e] && w[e] > bv) { bv = w[e]; best = e; }
            ord[j] = best; used[best] = true;
        }
        float sws[NE]; float cum = 0.f;
#pragma unroll
        for (int j = 0; j < NE; j++) {
            float tw = w[ord[j]];
            cum += tw;
            sws[j] = fmaxf(fminf(cum, CAP) - cum + tw, 0.f);
        }
#pragma unroll
        for (int e = 0; e < NE; e++) {
            float wt = sws[ord[e]];   // faithful take_along_axis(sw_sorted, order)
            if (wt > 0.f) {
                int pos = atomicAdd(&g_count[e], 1);
                g_list[e * N_TOK + pos] = n;
                g_wt [e * N_TOK + pos] = wt;
            }
        }
    }
}

// ---------------- HMMA expert GEMM ----------------
// 128x64 CTA tile, 4 warps (2 M x 2 N), 64x32 per warp, single fp16 A & B.
// A tile: 128 rows x 64B (sw64), 8KB. B tile: 32 k-rows x 128B [k][n] (sw128), 4KB.
// Stage 12KB; 4 stages = 48KB smem -> 4 CTAs/SM.
// PHASE 1 extra: blockIdx.z == NE carries W2 fp32->fp16 conversion.
// PHASE 2 epilogue: stage fp32 tile in smem (rows padded to 68 floats), then
// one thread per output row does 16x red.global.add.v4.f32.
#define A_TILE_B 8192
#define B_TILE_B 4096
#define STAGE_BYTES (A_TILE_B + B_TILE_B)  // 12KB
#define SMEM_BYTES  (STAGES * STAGE_BYTES) // 48KB
#define EPI_PITCH 68                        // floats per staged row (272B, 16B-aligned)

template<int PHASE>
__global__ __launch_bounds__(128, 4)
void moe_gemm(const float* __restrict__ bias, float* __restrict__ out,
              const float* __restrict__ W2src) {
    if (PHASE == 1 && blockIdx.z == NE) {
        size_t blk = (size_t)blockIdx.y * 64 + blockIdx.x;      // 0..1023
        size_t base = blk * 2048 + threadIdx.x;
#pragma unroll
        for (int it = 0; it < 16; it++) {
            size_t i = base + (size_t)it * 128;
            float4 v = reinterpret_cast<const float4*>(W2src)[i];
            __half h[4];
            h[0] = __float2half(v.x); h[1] = __float2half(v.y);
            h[2] = __float2half(v.z); h[3] = __float2half(v.w);
            *reinterpret_cast<uint2*>(&g_w2h[i * 4]) = *reinterpret_cast<uint2*>(h);
        }
        return;
    }

    int e = blockIdx.z;
    int cnt = g_count[e];
    int row0 = blockIdx.x * TM;
    if (row0 >= cnt) return;
    int n0 = blockIdx.y * TN;

    extern __shared__ char smem[];
    uint32_t sbase = smem_u32(smem);

    int tid = threadIdx.x, wid = tid >> 5, lane = tid & 31;

    // ---- A loader ----
    int seg = tid & 3;
    int r0l = tid >> 2;
    const __half* ahr[4];
    uint32_t sts_a[4];
#pragma unroll
    for (int q = 0; q < 4; q++) {
        int rl = r0l + 32 * q;         // 0..127
        int r = row0 + rl; if (r > cnt - 1) r = cnt - 1;
        if (PHASE == 1) {
            ahr[q] = g_xh + (size_t)g_list[e * N_TOK + r] * DMODEL;
        } else {
            ahr[q] = g_h + ((size_t)e * N_TOK + r) * DMODEL;
        }
        sts_a[q] = sw64((uint32_t)rl * 64 + seg * 16);
    }

    // ---- B loader: [k][n] tile ----
    const __half* gW = (PHASE == 1) ? g_w1h : g_w2h;
    const __half* bptr[2];
    uint32_t sts_b[2];
#pragma unroll
    for (int i = 0; i < 2; i++) {
        int u = tid + 128 * i;          // 0..255
        int kr = u >> 3;                // 0..31
        int sg = u & 7;
        bptr[i] = gW + ((size_t)e * DMODEL + kr) * DMODEL + n0 + sg * 8;
        sts_b[i] = sw128((uint32_t)kr * 128 + sg * 16);
    }

    auto load_stage = [&](int s, int c) {
        uint32_t st = sbase + s * STAGE_BYTES;
        int k0 = c * KC;
#pragma unroll
        for (int q = 0; q < 4; q++)
            CP16(st + sts_a[q], (const void*)(ahr[q] + k0 + seg * 8));
#pragma unroll
        for (int i = 0; i < 2; i++)
            CP16(st + A_TILE_B + sts_b[i], (const void*)(bptr[i] + (size_t)k0 * DMODEL));
    };

    // ---- compute setup ----
    int warpM = wid & 1;
    int warpN = wid >> 1;
    int a_row = (lane & 15);
    int kchunk16 = (lane >> 4) * 16;

    uint32_t arowb[4];
#pragma unroll
    for (int mt = 0; mt < 4; mt++)
        arowb[mt] = (uint32_t)(warpM * 64 + mt * 16 + a_row) * 64;

    int bkr = 8 * ((lane >> 4) & 1) + (lane & 7);
    uint32_t bco[2];
#pragma unroll
    for (int g = 0; g < 2; g++)
        bco[g] = (uint32_t)bkr * 128 + (uint32_t)(warpN * 32 + g * 16 + 8 * ((lane >> 3) & 1)) * 2;

    float acc[4][4][4];
#pragma unroll
    for (int mt = 0; mt < 4; mt++)
#pragma unroll
        for (int j = 0; j < 4; j++)
#pragma unroll
            for (int q = 0; q < 4; q++) acc[mt][j][q] = 0.f;

    // ---- pipeline ----
    load_stage(0, 0); CP_COMMIT();
    load_stage(1, 1); CP_COMMIT();
    load_stage(2, 2); CP_COMMIT();

    int s = 0;
    for (int c = 0; c < NCHUNK; ++c) {
        CP_WAIT2();
        __syncthreads();

        uint32_t st = sbase + s * STAGE_BYTES;
        uint32_t sA = st, sB = st + A_TILE_B;

#pragma unroll
        for (int k16 = 0; k16 < KC / 16; ++k16) {
            uint32_t koffA = (uint32_t)k16 * 32 + kchunk16;
            uint32_t koffB = (uint32_t)k16 * 2048;
            uint32_t bf[2][4];
#pragma unroll
            for (int g = 0; g < 2; g++)
                ldsm4t(bf[g], sB + sw128(bco[g] + koffB));
#pragma unroll
            for (int mt = 0; mt < 4; mt++) {
                uint32_t af[4];
                ldsm4(af, sA + sw64(arowb[mt] + koffA));
#pragma unroll
                for (int j = 0; j < 4; j++) {
                    int g = j >> 1, sub = j & 1;
                    mma16816(acc[mt][j], af, bf[g][0 + sub], bf[g][2 + sub]);
                }
            }
        }
        if (c + 3 < NCHUNK) load_stage((c + 3) % STAGES, c + 3);
        CP_COMMIT();
        if (++s == STAGES) s = 0;
    }

    // ---- epilogue ----
    int mrow_base = row0 + warpM * 64 + (lane >> 2);
    int ncol_base = n0 + warpN * 32 + (lane & 3) * 2;

    if (PHASE == 1) {
#pragma unroll
        for (int mt = 0; mt < 4; mt++) {
#pragma unroll
            for (int half = 0; half < 2; half++) {
                int r = mrow_base + mt * 16 + half * 8;
                if (r >= cnt) continue;
                size_t hb = ((size_t)e * N_TOK + r) * DMODEL;
#pragma unroll
                for (int j = 0; j < 4; j++) {
                    int ncol = ncol_base + j * 8;
                    float v0 = acc[mt][j][half * 2 + 0] + bias[e * DMODEL + ncol];
                    float v1 = acc[mt][j][half * 2 + 1] + bias[e * DMODEL + ncol + 1];
                    v0 = fmaxf(v0, 0.f); v1 = fmaxf(v1, 0.f);
                    __half2 hp;
                    hp.x = __float2half(v0); hp.y = __float2half(v1);
                    *reinterpret_cast<__half2*>(&g_h[hb + ncol]) = hp;
                }
            }
        }
    } else {
        // stage fp32 tile to smem (mainloop done; stage buffers reusable)
        __syncthreads();
        float* stg = reinterpret_cast<float*>(smem);
        int lrow_base = warpM * 64 + (lane >> 2);
        int lcol_base = warpN * 32 + (lane & 3) * 2;
#pragma unroll
        for (int mt = 0; mt < 4; mt++) {
#pragma unroll
            for (int half = 0; half < 2; half++) {
                int lr = lrow_base + mt * 16 + half * 8;
#pragma unroll
                for (int j = 0; j < 4; j++) {
                    float2 v = make_float2(acc[mt][j][half * 2 + 0],
                                           acc[mt][j][half * 2 + 1]);
                    *reinterpret_cast<float2*>(&stg[lr * EPI_PITCH + lcol_base + j * 8]) = v;
                }
            }
        }
        __syncthreads();
        int r = row0 + tid;
        if (r < cnt) {
            int tok = g_list[e * N_TOK + r];
            float wt = g_wt[e * N_TOK + r];
            const float4* brow = reinterpret_cast<const float4*>(bias + e * DMODEL + n0);
            float* orow = out + (size_t)tok * DMODEL + n0;
            const float4* srow = reinterpret_cast<const float4*>(&stg[tid * EPI_PITCH]);
#pragma unroll
            for (int i = 0; i < 16; i++) {
                float4 a = srow[i];
                float4 b = brow[i];
                float4 v = make_float4(wt * (a.x + b.x), wt * (a.y + b.y),
                                       wt * (a.z + b.z), wt * (a.w + b.w));
                red_add_v4(orow + i * 4, v);
            }
        }
    }
}

// ---------------- launch ----------------
extern "C" void kernel_launch(void* const* d_in, const int* in_sizes, int n_in,
                              void* d_out, int out_size) {
    const float* x    = (const float*)d_in[0];
    const float* Wsel = (const float*)d_in[1];
    const float* bsel = (const float*)d_in[2];
    const float* W1   = (const float*)d_in[3];
    const float* b1   = (const float*)d_in[4];
    const float* W2   = (const float*)d_in[5];
    const float* b2   = (const float*)d_in[6];
    float* out = (float*)d_out;

    cudaFuncSetAttribute(moe_gemm<1>, cudaFuncAttributeMaxDynamicSharedMemorySize, SMEM_BYTES);
    cudaFuncSetAttribute(moe_gemm<2>, cudaFuncAttributeMaxDynamicSharedMemorySize, SMEM_BYTES);

    zero_counts_kernel<<<1, 32>>>();
    pre_kernel<<<ROUTER_BLOCKS + W1CONV_BLOCKS + OUTZ_BLOCKS, 256>>>(x, Wsel, bsel, W1, out);

    dim3 g1(N_TOK / TM, DMODEL / TN, NE + 1);
    moe_gemm<1><<<g1, 128, SMEM_BYTES>>>(b1, nullptr, W2);

    dim3 g2(N_TOK / TM, DMODEL / TN, NE);
    moe_gemm<2><<<g2, 128, SMEM_BYTES>>>(b2, out, nullptr);
}

// round 16
// speedup vs baseline: 1.0425x; 1.0425x over previous
#include <cuda_runtime.h>
#include <cuda_bf16.h>
#include <cuda_fp16.h>
#include <cstdint>

#define N_TOK  8192
#define DMODEL 1024
#define NE     8
#define CAP    0.8f

#define TM 128
#define TN 64
#define KC 32
#define NCHUNK (DMODEL / KC)   // 32
#define STAGES 4

// ---------------- device scratch (allocation-free rule) ----------------
__device__ int   g_count[NE];
__device__ int   g_list[NE * N_TOK];
__device__ float g_wt  [NE * N_TOK];
__device__ __half g_xh[(size_t)N_TOK * DMODEL];
__device__ __half g_w1h[(size_t)NE * DMODEL * DMODEL];   // [e][k][n] native layout
__device__ __half g_w2h[(size_t)NE * DMODEL * DMODEL];   // [e][k][n] native layout
__device__ __half g_h  [(size_t)NE * N_TOK * DMODEL];

// ---------------- helpers ----------------
__device__ __forceinline__ uint32_t smem_u32(const void* p) {
    uint32_t a;
    asm("{ .reg .u64 t; cvta.to.shared.u64 t, %1; cvt.u32.u64 %0, t; }" : "=r"(a) : "l"(p));
    return a;
}
__device__ __forceinline__ uint32_t sw64(uint32_t off)  { return off ^ ((off >> 3) & 0x30); }
__device__ __forceinline__ uint32_t sw128(uint32_t off) { return off ^ ((off >> 3) & 0x70); }

#define CP16(dst, src) \
    asm volatile("cp.async.cg.shared.global [%0], [%1], 16;" :: "r"(dst), "l"(src) : "memory")
#define CP_COMMIT() asm volatile("cp.async.commit_group;" ::: "memory")
#define CP_WAIT2()  asm volatile("cp.async.wait_group 2;" ::: "memory")

__device__ __forceinline__ void ldsm4(uint32_t (&r)[4], uint32_t addr) {
    asm volatile("ldmatrix.sync.aligned.m8n8.x4.shared.b16 {%0,%1,%2,%3}, [%4];"
                 : "=r"(r[0]), "=r"(r[1]), "=r"(r[2]), "=r"(r[3]) : "r"(addr));
}
__device__ __forceinline__ void ldsm4t(uint32_t (&r)[4], uint32_t addr) {
    asm volatile("ldmatrix.sync.aligned.m8n8.x4.trans.shared.b16 {%0,%1,%2,%3}, [%4];"
                 : "=r"(r[0]), "=r"(r[1]), "=r"(r[2]), "=r"(r[3]) : "r"(addr));
}
__device__ __forceinline__ void mma16816(float* d, const uint32_t* a, uint32_t b0, uint32_t b1) {
    asm volatile(
        "mma.sync.aligned.m16n8k16.row.col.f32.f16.f16.f32 "
        "{%0,%1,%2,%3}, {%4,%5,%6,%7}, {%8,%9}, {%0,%1,%2,%3};"
        : "+f"(d[0]), "+f"(d[1]), "+f"(d[2]), "+f"(d[3])
        : "r"(a[0]), "r"(a[1]), "r"(a[2]), "r"(a[3]), "r"(b0), "r"(b1));
}

// ---------------- zero counts ----------------
__global__ void zero_counts_kernel() {
    if (threadIdx.x < NE) g_count[threadIdx.x] = 0;
}

// ---------------- pre: router + W1 convert + out zero (one launch) ----------------
// blocks [0, 1024): router ; [1024, 3072): W1 convert ; [3072, 4096): zero out
#define ROUTER_BLOCKS 1024
#define W1CONV_BLOCKS 2048
#define OUTZ_BLOCKS   1024

__global__ void pre_kernel(const float* __restrict__ x,
                           const float* __restrict__ Wsel,
                           const float* __restrict__ bsel,
                           const float* __restrict__ W1,
                           float* __restrict__ out) {
    int bid = blockIdx.x;
    if (bid >= ROUTER_BLOCKS + W1CONV_BLOCKS) {
        size_t base = (size_t)(bid - ROUTER_BLOCKS - W1CONV_BLOCKS) * 2048 + threadIdx.x;
        float4 z = make_float4(0.f, 0.f, 0.f, 0.f);
#pragma unroll
        for (int it = 0; it < 8; it++)
            reinterpret_cast<float4*>(out)[base + (size_t)it * 256] = z;
        return;
    }
    if (bid >= ROUTER_BLOCKS) {
        size_t base = (size_t)(bid - ROUTER_BLOCKS) * 1024 + threadIdx.x;
#pragma unroll
        for (int it = 0; it < 4; it++) {
            size_t i = base + (size_t)it * 256;
            float4 v = reinterpret_cast<const float4*>(W1)[i];
            __half h[4];
            h[0] = __float2half(v.x); h[1] = __float2half(v.y);
            h[2] = __float2half(v.z); h[3] = __float2half(v.w);
            *reinterpret_cast<uint2*>(&g_w1h[i * 4]) = *reinterpret_cast<uint2*>(h);
        }
        return;
    }

    // ---- router: 8 warps = 8 tokens per block ----
    int warp = threadIdx.x >> 5;
    int lane = threadIdx.x & 31;
    int n = bid * 8 + warp;

    const float* xr = x + (size_t)n * DMODEL;
    __half* xo = g_xh + (size_t)n * DMODEL;
    float acc[NE];
#pragma unroll
    for (int e = 0; e < NE; e++) acc[e] = 0.f;
    for (int d = lane * 2; d < DMODEL; d += 64) {
        float2 xv = *reinterpret_cast<const float2*>(xr + d);
        __half2 hx;
        hx.x = __float2half(xv.x); hx.y = __float2half(xv.y);
        *reinterpret_cast<__half2*>(xo + d) = hx;
        const float4* w4 = reinterpret_cast<const float4*>(Wsel + (size_t)d * NE);
        float4 a0 = w4[0], a1 = w4[1];
        float4 c0 = w4[2], c1 = w4[3];
        acc[0] += xv.x * a0.x; acc[1] += xv.x * a0.y; acc[2] += xv.x * a0.z; acc[3] += xv.x * a0.w;
        acc[4] += xv.x * a1.x; acc[5] += xv.x * a1.y; acc[6] += xv.x * a1.z; acc[7] += xv.x * a1.w;
        acc[0] += xv.y * c0.x; acc[1] += xv.y * c0.y; acc[2] += xv.y * c0.z; acc[3] += xv.y * c0.w;
        acc[4] += xv.y * c1.x; acc[5] += xv.y * c1.y; acc[6] += xv.y * c1.z; acc[7] += xv.y * c1.w;
    }
#pragma unroll
    for (int off = 16; off; off >>= 1)
#pragma unroll
        for (int e = 0; e < NE; e++) acc[e] += __shfl_xor_sync(0xffffffffu, acc[e], off);

    if (lane == 0) {
        float w[NE];
        float mx = -1e30f;
#pragma unroll
        for (int e = 0; e < NE; e++) { w[e] = acc[e] + bsel[e]; mx = fmaxf(mx, w[e]); }
        float s = 0.f;
#pragma unroll
        for (int e = 0; e < NE; e++) { w[e] = expf(w[e] - mx); s += w[e]; }
        float inv = 1.f / s;
#pragma unroll
        for (int e = 0; e < NE; e++) w[e] *= inv;

        int ord[NE]; bool used[NE];
#pragma unroll
        for (int e = 0; e < NE; e++) used[e] = false;
#pragma unroll
        for (int j = 0; j < NE; j++) {
            int best = -1; float bv = -1e30f;
#pragma unroll
            for (int e = 0; e < NE; e++)
                if (!used[e] && w[e] > bv) { bv = w[e]; best = e; }
            ord[j] = best; used[best] = true;
        }
        float sws[NE]; float cum = 0.f;
#pragma unroll
        for (int j = 0; j < NE; j++) {
            float tw = w[ord[j]];
            cum += tw;
            sws[j] = fmaxf(fminf(cum, CAP) - cum + tw, 0.f);
        }
#pragma unroll
        for (int e = 0; e < NE; e++) {
            float wt = sws[ord[e]];   // faithful take_along_axis(sw_sorted, order)
            if (wt > 0.f) {
                int pos = atomicAdd(&g_count[e], 1);
                g_list[e * N_TOK + pos] = n;
                g_wt [e * N_TOK + pos] = wt;
            }
        }
    }
}

// ---------------- HMMA expert GEMM ----------------
// 128x64 CTA tile, 4 warps (2 M x 2 N), 64x32 per warp, single fp16 A & B.
// A tile: 128 rows x 64B (sw64), 8KB. B tile: 32 k-rows x 128B [k][n] (sw128), 4KB.
// Stage 12KB; 4 stages = 48KB smem -> 4 CTAs/SM.
// PHASE 1 extra: blockIdx.z == NE carries W2 fp32->fp16 conversion.
#define A_TILE_B 8192
#define B_TILE_B 4096
#define STAGE_BYTES (A_TILE_B + B_TILE_B)  // 12KB
#define SMEM_BYTES  (STAGES * STAGE_BYTES) // 48KB

template<int PHASE>
__global__ __launch_bounds__(128, 4)
void moe_gemm(const float* __restrict__ bias, float* __restrict__ out,
              const float* __restrict__ W2src) {
    if (PHASE == 1 && blockIdx.z == NE) {
        size_t blk = (size_t)blockIdx.y * 64 + blockIdx.x;      // 0..1023
        size_t base = blk * 2048 + threadIdx.x;
#pragma unroll
        for (int it = 0; it < 16; it++) {
            size_t i = base + (size_t)it * 128;
            float4 v = reinterpret_cast<const float4*>(W2src)[i];
            __half h[4];
            h[0] = __float2half(v.x); h[1] = __float2half(v.y);
            h[2] = __float2half(v.z); h[3] = __float2half(v.w);
            *reinterpret_cast<uint2*>(&g_w2h[i * 4]) = *reinterpret_cast<uint2*>(h);
        }
        return;
    }

    int e = blockIdx.z;
    int cnt = g_count[e];
    int row0 = blockIdx.x * TM;
    if (row0 >= cnt) return;
    int n0 = blockIdx.y * TN;

    extern __shared__ char smem[];
    uint32_t sbase = smem_u32(smem);

    int tid = threadIdx.x, wid = tid >> 5, lane = tid & 31;

    // ---- A loader ----
    int seg = tid & 3;
    int r0l = tid >> 2;
    const __half* ahr[4];
    uint32_t sts_a[4];
#pragma unroll
    for (int q = 0; q < 4; q++) {
        int rl = r0l + 32 * q;         // 0..127
        int r = row0 + rl; if (r > cnt - 1) r = cnt - 1;
        if (PHASE == 1) {
            ahr[q] = g_xh + (size_t)g_list[e * N_TOK + r] * DMODEL;
        } else {
            ahr[q] = g_h + ((size_t)e * N_TOK + r) * DMODEL;
        }
        sts_a[q] = sw64((uint32_t)rl * 64 + seg * 16);
    }

    // ---- B loader: [k][n] tile ----
    const __half* gW = (PHASE == 1) ? g_w1h : g_w2h;
    const __half* bptr[2];
    uint32_t sts_b[2];
#pragma unroll
    for (int i = 0; i < 2; i++) {
        int u = tid + 128 * i;          // 0..255
        int kr = u >> 3;                // 0..31
        int sg = u & 7;
        bptr[i] = gW + ((size_t)e * DMODEL + kr) * DMODEL + n0 + sg * 8;
        sts_b[i] = sw128((uint32_t)kr * 128 + sg * 16);
    }

    auto load_stage = [&](int s, int c) {
        uint32_t st = sbase + s * STAGE_BYTES;
        int k0 = c * KC;
#pragma unroll
        for (int q = 0; q < 4; q++)
            CP16(st + sts_a[q], (const void*)(ahr[q] + k0 + seg * 8));
#pragma unroll
        for (int i = 0; i < 2; i++)
            CP16(st + A_TILE_B + sts_b[i], (const void*)(bptr[i] + (size_t)k0 * DMODEL));
    };

    // ---- compute setup ----
    int warpM = wid & 1;
    int warpN = wid >> 1;
    int a_row = (lane & 15);
    int kchunk16 = (lane >> 4) * 16;

    uint32_t arowb[4];
#pragma unroll
    for (int mt = 0; mt < 4; mt++)
        arowb[mt] = (uint32_t)(warpM * 64 + mt * 16 + a_row) * 64;

    int bkr = 8 * ((lane >> 4) & 1) + (lane & 7);
    uint32_t bco[2];
#pragma unroll
    for (int g = 0; g < 2; g++)
        bco[g] = (uint32_t)bkr * 128 + (uint32_t)(warpN * 32 + g * 16 + 8 * ((lane >> 3) & 1)) * 2;

    float acc[4][4][4];
#pragma unroll
    for (int mt = 0; mt < 4; mt++)
#pragma unroll
        for (int j = 0; j < 4; j++)
#pragma unroll
            for (int q = 0; q < 4; q++) acc[mt][j][q] = 0.f;

    // ---- pipeline ----
    load_stage(0, 0); CP_COMMIT();
    load_stage(1, 1); CP_COMMIT();
    load_stage(2, 2); CP_COMMIT();

    int s = 0;
    for (int c = 0; c < NCHUNK; ++c) {
        CP_WAIT2();
        __syncthreads();

        uint32_t st = sbase + s * STAGE_BYTES;
        uint32_t sA = st, sB = st + A_TILE_B;

#pragma unroll
        for (int k16 = 0; k16 < KC / 16; ++k16) {
            uint32_t koffA = (uint32_t)k16 * 32 + kchunk16;
            uint32_t koffB = (uint32_t)k16 * 2048;
            uint32_t bf[2][4];
#pragma unroll
            for (int g = 0; g < 2; g++)
                ldsm4t(bf[g], sB + sw128(bco[g] + koffB));
#pragma unroll
            for (int mt = 0; mt < 4; mt++) {
                uint32_t af[4];
                ldsm4(af, sA + sw64(arowb[mt] + koffA));
#pragma unroll
                for (int j = 0; j < 4; j++) {
                    int g = j >> 1, sub = j & 1;
                    mma16816(acc[mt][j], af, bf[g][0 + sub], bf[g][2 + sub]);
                }
            }
        }
        if (c + 3 < NCHUNK) load_stage((c + 3) % STAGES, c + 3);
        CP_COMMIT();
        if (++s == STAGES) s = 0;
    }

    // ---- epilogue (bias hoisted: 4 float2 loads per thread, reused 8x) ----
    int mrow_base = row0 + warpM * 64 + (lane >> 2);
    int ncol_base = n0 + warpN * 32 + (lane & 3) * 2;

    float2 bj[4];
#pragma unroll
    for (int j = 0; j < 4; j++)
        bj[j] = *reinterpret_cast<const float2*>(bias + e * DMODEL + ncol_base + j * 8);

    if (PHASE == 1) {
#pragma unroll
        for (int mt = 0; mt < 4; mt++) {
#pragma unroll
            for (int half = 0; half < 2; half++) {
                int r = mrow_base + mt * 16 + half * 8;
                if (r >= cnt) continue;
                size_t hb = ((size_t)e * N_TOK + r) * DMODEL;
#pragma unroll
                for (int j = 0; j < 4; j++) {
                    int ncol = ncol_base + j * 8;
                    float v0 = acc[mt][j][half * 2 + 0] + bj[j].x;
                    float v1 = acc[mt][j][half * 2 + 1] + bj[j].y;
                    v0 = fmaxf(v0, 0.f); v1 = fmaxf(v1, 0.f);
                    __half2 hp;
                    hp.x = __float2half(v0); hp.y = __float2half(v1);
                    *reinterpret_cast<__half2*>(&g_h[hb + ncol]) = hp;
                }
            }
        }
    } else {
#pragma unroll
        for (int mt = 0; mt < 4; mt++) {
#pragma unroll
            for (int half = 0; half < 2; half++) {
                int r = mrow_base + mt * 16 + half * 8;
                if (r >= cnt) continue;
                int tok = g_list[e * N_TOK + r];
                float wt = g_wt[e * N_TOK + r];
                float* orow = out + (size_t)tok * DMODEL;
#pragma unroll
                for (int j = 0; j < 4; j++) {
                    int ncol = ncol_base + j * 8;
                    float y0 = acc[mt][j][half * 2 + 0] + bj[j].x;
                    float y1 = acc[mt][j][half * 2 + 1] + bj[j].y;
                    float2 v = make_float2(wt * y0, wt * y1);
                    atomicAdd(reinterpret_cast<float2*>(orow + ncol), v);
                }
            }
        }
    }
}

// ---------------- launch ----------------
extern "C" void kernel_launch(void* const* d_in, const int* in_sizes, int n_in,
                              void* d_out, int out_size) {
    const float* x    = (const float*)d_in[0];
    const float* Wsel = (const float*)d_in[1];
    const float* bsel = (const float*)d_in[2];
    const float* W1   = (const float*)d_in[3];
    const float* b1   = (const float*)d_in[4];
    const float* W2   = (const float*)d_in[5];
    const float* b2   = (const float*)d_in[6];
    float* out = (float*)d_out;

    cudaFuncSetAttribute(moe_gemm<1>, cudaFuncAttributeMaxDynamicSharedMemorySize, SMEM_BYTES);
    cudaFuncSetAttribute(moe_gemm<2>, cudaFuncAttributeMaxDynamicSharedMemorySize, SMEM_BYTES);

    zero_counts_kernel<<<1, 32>>>();
    pre_kernel<<<ROUTER_BLOCKS + W1CONV_BLOCKS + OUTZ_BLOCKS, 256>>>(x, Wsel, bsel, W1, out);

    dim3 g1(N_TOK / TM, DMODEL / TN, NE + 1);
    moe_gemm<1><<<g1, 128, SMEM_BYTES>>>(b1, nullptr, W2);

    dim3 g2(N_TOK / TM, DMODEL / TN, NE);
    moe_gemm<2><<<g2, 128, SMEM_BYTES>>>(b2, out, nullptr);
}